// round 1
// baseline (speedup 1.0000x reference)
#include <cuda_runtime.h>

#define BATCH 256
#define SEQ   2048
#define EMBD  16
#define HIDD  32
#define GATE  128

typedef unsigned long long u64;

__device__ __forceinline__ u64 pack2(float lo, float hi){
    u64 r; asm("mov.b64 %0, {%1,%2};" : "=l"(r) : "f"(lo), "f"(hi)); return r;
}
__device__ __forceinline__ void unpack2(u64 v, float& lo, float& hi){
    asm("mov.b64 {%0,%1}, %2;" : "=f"(lo), "=f"(hi) : "l"(v));
}
__device__ __forceinline__ u64 ffma2(u64 a, u64 b, u64 c){
    u64 d; asm("fma.rn.f32x2 %0, %1, %2, %3;" : "=l"(d) : "l"(a), "l"(b), "l"(c)); return d;
}
__device__ __forceinline__ u64 fadd2(u64 a, u64 b){
    u64 d; asm("add.rn.f32x2 %0, %1, %2;" : "=l"(d) : "l"(a), "l"(b)); return d;
}

__device__ __forceinline__ float sigf(float z){
    return __fdividef(1.0f, 1.0f + __expf(-z));
}
__device__ __forceinline__ float tanhf_fast(float z){
    return __fdividef(2.0f, 1.0f + __expf(-2.0f * z)) - 1.0f;
}

// One warp per batch sequence. Lane j owns hid index j and gate columns
// (j, j+32, j+64, j+96) packed as two f32x2 accumulators -> gate update is
// entirely lane-local. h broadcast via shared {h,h} pairs (LDS.64 broadcast),
// double-buffered so a single __syncwarp per timestep suffices.
__global__ __launch_bounds__(32) void lstm_fused_kernel(
    const int*   __restrict__ tokens,
    const float* __restrict__ emb,
    const float* __restrict__ Wk,
    const float* __restrict__ Wr,
    const float* __restrict__ bias,
    float*       __restrict__ out)
{
    __shared__ u64 sWk_if[EMBD][HIDD];
    __shared__ u64 sWk_go[EMBD][HIDD];
    __shared__ u64 h2[2][HIDD];
    __shared__ u64 x2[2][EMBD];

    const int b = blockIdx.x;
    const int j = threadIdx.x;

    // Pre-pack Wk columns (j, j+32) and (j+64, j+96) into shared as f32x2.
    #pragma unroll
    for (int e = 0; e < EMBD; e++){
        sWk_if[e][j] = pack2(Wk[e*GATE + j],      Wk[e*GATE + j + 32]);
        sWk_go[e][j] = pack2(Wk[e*GATE + j + 64], Wk[e*GATE + j + 96]);
    }
    // Wr columns live in registers (64 x u64 = 128 fp32 regs).
    u64 wr_if[HIDD], wr_go[HIDD];
    #pragma unroll
    for (int k = 0; k < HIDD; k++){
        wr_if[k] = pack2(Wr[k*GATE + j],      Wr[k*GATE + j + 32]);
        wr_go[k] = pack2(Wr[k*GATE + j + 64], Wr[k*GATE + j + 96]);
    }
    const u64 b_if  = pack2(bias[j],      bias[j + 32]);
    const u64 b_go  = pack2(bias[j + 64], bias[j + 96]);
    const u64 zero2 = pack2(0.0f, 0.0f);

    const int* tptr = tokens + b * SEQ;
    float* optr = out + ((size_t)b * SEQ) * HIDD + j;

    // Prime: token for t=0 and t=1, embedding row for t=0, h = 0.
    int tokA = tptr[0];
    int tokB = tptr[1];
    if (j < EMBD){
        float x0 = emb[tokA * EMBD + j];
        x2[0][j] = pack2(x0, x0);
    }
    h2[0][j] = zero2;
    __syncwarp();

    float h = 0.0f, c = 0.0f;

    for (int t = 0; t < SEQ; t++){
        const int rb = t & 1, wb = rb ^ 1;
        const int tok_cur = tokA;
        // Prefetch: token t+2, embedding row for t+1 (one full step of latency cover).
        const int t2   = (t + 2 < SEQ) ? (t + 2) : (SEQ - 1);
        const int tokC = tptr[t2];
        float xn = 0.0f;
        if (j < EMBD) xn = emb[tokB * EMBD + j];

        // z = b + Wk^T x + Wr^T h, packed (i,f) and (g,o), 2 acc chains each.
        u64 aI = b_if,  aG = b_go;
        u64 bI = zero2, bG = zero2;

        #pragma unroll
        for (int e = 0; e < EMBD; e += 2){
            u64 xe0 = x2[rb][e];
            u64 xe1 = x2[rb][e + 1];
            aI = ffma2(xe0, sWk_if[e][j],     aI);
            aG = ffma2(xe0, sWk_go[e][j],     aG);
            bI = ffma2(xe1, sWk_if[e + 1][j], bI);
            bG = ffma2(xe1, sWk_go[e + 1][j], bG);
        }
        #pragma unroll
        for (int k = 0; k < HIDD; k += 2){
            u64 hk0 = h2[rb][k];
            u64 hk1 = h2[rb][k + 1];
            aI = ffma2(hk0, wr_if[k],     aI);
            aG = ffma2(hk0, wr_go[k],     aG);
            bI = ffma2(hk1, wr_if[k + 1], bI);
            bG = ffma2(hk1, wr_go[k + 1], bG);
        }

        // Stash prefetched x for step t+1 (write buffer, protected by end sync).
        if (j < EMBD) x2[wb][j] = pack2(xn, xn);

        u64 zIF = fadd2(aI, bI);
        u64 zGO = fadd2(aG, bG);
        float zi, zf, zg, zo;
        unpack2(zIF, zi, zf);
        unpack2(zGO, zg, zo);

        float gi = sigf(zi);
        float gf = sigf(zf);
        float gg = tanhf_fast(zg);
        float go = sigf(zo);
        float cn = gf * c + gi * gg;
        float hn = go * tanhf_fast(cn);

        if (tok_cur != 0){ h = hn; c = cn; }

        optr[(size_t)t * HIDD] = h;          // coalesced 128B per warp
        h2[wb][j] = pack2(h, h);

        tokA = tokB; tokB = tokC;
        __syncwarp();
    }
}

extern "C" void kernel_launch(void* const* d_in, const int* in_sizes, int n_in,
                              void* d_out, int out_size)
{
    (void)in_sizes; (void)n_in; (void)out_size;
    const int*   tokens = (const int*)  d_in[0];
    const float* emb    = (const float*)d_in[1];
    const float* Wk     = (const float*)d_in[2];
    const float* Wr     = (const float*)d_in[3];
    const float* bias   = (const float*)d_in[4];
    float* out = (float*)d_out;

    lstm_fused_kernel<<<BATCH, 32>>>(tokens, emb, Wk, Wr, bias, out);
}

// round 2
// speedup vs baseline: 1.3790x; 1.3790x over previous
#include <cuda_runtime.h>

#define BATCH 256
#define SEQ   2048
#define EMBD  16
#define HIDD  32
#define GATE  128

typedef unsigned long long u64;

// 256 MB gate-interleaved input projection scratch: float4(i,f,g,o) per (token, j)
__device__ float4 g_zx[(size_t)BATCH * SEQ * HIDD];

__device__ __forceinline__ u64 pack2(float lo, float hi){
    u64 r; asm("mov.b64 %0, {%1,%2};" : "=l"(r) : "f"(lo), "f"(hi)); return r;
}
__device__ __forceinline__ void unpack2(u64 v, float& lo, float& hi){
    asm("mov.b64 {%0,%1}, %2;" : "=f"(lo), "=f"(hi) : "l"(v));
}
__device__ __forceinline__ u64 ffma2(u64 a, u64 b, u64 c){
    u64 d; asm("fma.rn.f32x2 %0, %1, %2, %3;" : "=l"(d) : "l"(a), "l"(b), "l"(c)); return d;
}
__device__ __forceinline__ u64 fadd2(u64 a, u64 b){
    u64 d; asm("add.rn.f32x2 %0, %1, %2;" : "=l"(d) : "l"(a), "l"(b)); return d;
}
__device__ __forceinline__ float tanha(float x){
    float y; asm("tanh.approx.f32 %0, %1;" : "=f"(y) : "f"(x)); return y;
}
// sigmoid(z) = 0.5 + 0.5*tanh(z/2)  (exact identity; tanh via MUFU.TANH)
__device__ __forceinline__ float sigt(float z){
    return fmaf(0.5f, tanha(0.5f * z), 0.5f);
}

// ────────────────────────── Phase 1: zx = emb[tok] @ Wk + b ──────────────────
// Grid 256 x 256 threads (8 warps). Each warp owns 256 consecutive flat tokens,
// processes 2 per iteration (lanes 0-15 load x of token A, 16-31 token B; x
// broadcast via shfl). Lane j computes gate columns (j, j+32, j+64, j+96),
// stores float4(i,f,g,o) -> phase 2 reads one LDG.128 per lane per step.
__global__ __launch_bounds__(256) void proj_kernel(
    const int*   __restrict__ tokens,
    const float* __restrict__ emb,
    const float* __restrict__ Wk,
    const float* __restrict__ bias)
{
    const int j    = threadIdx.x & 31;
    const int warp = (blockIdx.x << 3) + (threadIdx.x >> 5);
    const int base = warp << 8;                  // 256 tokens per warp

    u64 wk_if[EMBD], wk_go[EMBD];
    #pragma unroll
    for (int e = 0; e < EMBD; e++){
        wk_if[e] = pack2(Wk[e*GATE + j],      Wk[e*GATE + j + 32]);
        wk_go[e] = pack2(Wk[e*GATE + j + 64], Wk[e*GATE + j + 96]);
    }
    const u64 b_if = pack2(bias[j],      bias[j + 32]);
    const u64 b_go = pack2(bias[j + 64], bias[j + 96]);

    for (int s = 0; s < 256; s += 2){
        const int tflat = base + s + (j >> 4);   // lanes 0-15: s, 16-31: s+1
        const int tok   = tokens[tflat];
        const float xv  = emb[tok * EMBD + (j & 15)];

        u64 aI = b_if, aG = b_go;                // token A
        u64 cI = b_if, cG = b_go;                // token B
        #pragma unroll
        for (int e = 0; e < EMBD; e++){
            float xa = __shfl_sync(0xffffffffu, xv, e);
            float xb = __shfl_sync(0xffffffffu, xv, 16 + e);
            u64 xa2 = pack2(xa, xa);
            u64 xb2 = pack2(xb, xb);
            aI = ffma2(xa2, wk_if[e], aI);
            aG = ffma2(xa2, wk_go[e], aG);
            cI = ffma2(xb2, wk_if[e], cI);
            cG = ffma2(xb2, wk_go[e], cG);
        }
        float4 zA, zB;
        unpack2(aI, zA.x, zA.y); unpack2(aG, zA.z, zA.w);
        unpack2(cI, zB.x, zB.y); unpack2(cG, zB.z, zB.w);
        g_zx[(size_t)(base + s)     * HIDD + j] = zA;
        g_zx[(size_t)(base + s + 1) * HIDD + j] = zB;
    }
}

// ────────────────────────── Phase 2: masked LSTM recurrence ──────────────────
// One warp per sequence. Lane j owns hid j and gate cols (j,j+32,j+64,j+96).
// zx + tokens prefetched 3 steps ahead into register rings; h broadcast via
// double-buffered {h,h} smem pairs; gates via MUFU.TANH; Wr matvec as 4
// independent 8-deep FFMA2 chains per packed gate pair.
__global__ __launch_bounds__(32) void rec_kernel(
    const int*   __restrict__ tokens,
    const float* __restrict__ Wr,
    float*       __restrict__ out)
{
    __shared__ u64 h2[2][HIDD];

    const int b = blockIdx.x;
    const int j = threadIdx.x;

    u64 wr_if[HIDD], wr_go[HIDD];
    #pragma unroll
    for (int k = 0; k < HIDD; k++){
        wr_if[k] = pack2(Wr[k*GATE + j],      Wr[k*GATE + j + 32]);
        wr_go[k] = pack2(Wr[k*GATE + j + 64], Wr[k*GATE + j + 96]);
    }

    const float4* __restrict__ zp = g_zx + (size_t)b * SEQ * HIDD + j;
    const int*    __restrict__ tptr = tokens + b * SEQ;
    float* optr = out + (size_t)b * SEQ * HIDD + j;

    h2[0][j] = pack2(0.0f, 0.0f);
    __syncwarp();

    float4 rz[4];
    int    rtok[4];
    #pragma unroll
    for (int p = 0; p < 3; p++){
        rz[p]   = zp[(size_t)p * HIDD];
        rtok[p] = tptr[p];
    }

    float h = 0.0f, c = 0.0f;

    #pragma unroll 4
    for (int t = 0; t < SEQ; t++){
        const int rb = t & 1, wb = rb ^ 1;
        const int slot = t & 3;

        // Prefetch t+3 (independent of recurrence; hides L2/DRAM latency).
        if (t + 3 < SEQ){
            rz[(t + 3) & 3]   = zp[(size_t)(t + 3) * HIDD];
            rtok[(t + 3) & 3] = tptr[t + 3];
        }
        const float4 z4  = rz[slot];
        const int    tok = rtok[slot];

        // Wr matvec: 4 independent chains per packed pair.
        u64 aI0 = 0, aI1 = 0, aI2 = 0, aI3 = 0;
        u64 aG0 = 0, aG1 = 0, aG2 = 0, aG3 = 0;
        #pragma unroll
        for (int k = 0; k < HIDD; k += 4){
            u64 h0 = h2[rb][k];
            u64 h1 = h2[rb][k + 1];
            u64 h2v = h2[rb][k + 2];
            u64 h3 = h2[rb][k + 3];
            aI0 = ffma2(h0,  wr_if[k],     aI0);
            aG0 = ffma2(h0,  wr_go[k],     aG0);
            aI1 = ffma2(h1,  wr_if[k + 1], aI1);
            aG1 = ffma2(h1,  wr_go[k + 1], aG1);
            aI2 = ffma2(h2v, wr_if[k + 2], aI2);
            aG2 = ffma2(h2v, wr_go[k + 2], aG2);
            aI3 = ffma2(h3,  wr_if[k + 3], aI3);
            aG3 = ffma2(h3,  wr_go[k + 3], aG3);
        }
        u64 zIF = fadd2(fadd2(aI0, aI1), fadd2(aI2, aI3));
        u64 zGO = fadd2(fadd2(aG0, aG1), fadd2(aG2, aG3));
        zIF = fadd2(zIF, pack2(z4.x, z4.y));
        zGO = fadd2(zGO, pack2(z4.z, z4.w));

        float zi, zf, zg, zo;
        unpack2(zIF, zi, zf);
        unpack2(zGO, zg, zo);

        const float gi = sigt(zi);
        const float gf = sigt(zf);
        const float gg = tanha(zg);
        const float go = sigt(zo);
        const float cn = fmaf(gf, c, gi * gg);
        const float hn = go * tanha(cn);

        if (tok != 0){ h = hn; c = cn; }

        optr[(size_t)t * HIDD] = h;
        h2[wb][j] = pack2(h, h);
        __syncwarp();
    }
}

extern "C" void kernel_launch(void* const* d_in, const int* in_sizes, int n_in,
                              void* d_out, int out_size)
{
    (void)in_sizes; (void)n_in; (void)out_size;
    const int*   tokens = (const int*)  d_in[0];
    const float* emb    = (const float*)d_in[1];
    const float* Wk     = (const float*)d_in[2];
    const float* Wr     = (const float*)d_in[3];
    const float* bias   = (const float*)d_in[4];
    float* out = (float*)d_out;

    proj_kernel<<<BATCH, 256>>>(tokens, emb, Wk, bias);
    rec_kernel<<<BATCH, 32>>>(tokens, Wr, out);
}